// round 2
// baseline (speedup 1.0000x reference)
#include <cuda_runtime.h>
#include <stdint.h>

#define HID 256
#define OUTC 896
#define N_MAX 100000
#define NPAD_MAX 100096   // 782 * 128
#define NNZ_MAX 3200000

// ---------------- device scratch (no allocation allowed) ----------------
__device__ float g_bufA[(size_t)NPAD_MAX * HID];   // layer input  h
__device__ float g_bufB[(size_t)NPAD_MAX * HID];   // spmm+dropout m
__device__ int   g_cnt[N_MAX];
__device__ int   g_rowptr[N_MAX + 1];
__device__ int   g_rowfill[N_MAX];
__device__ int   g_ccol[NNZ_MAX];
__device__ float g_cval[NNZ_MAX];

// ---------------- threefry2x32 (JAX-exact, 20 rounds) ----------------
// Partitionable-mode draw: plaintext (x0,x1) = (0, i); returns folded b1^b2.
__device__ __forceinline__ uint32_t tf20_fold(uint32_t k0, uint32_t k1, uint32_t i) {
    uint32_t k2 = k0 ^ k1 ^ 0x1BD11BDAu;
    uint32_t x0 = k0;        // 0 + k0
    uint32_t x1 = i + k1;
#define R4(a,b,c,d) \
    x0 += x1; x1 = __funnelshift_l(x1, x1, (a)); x1 ^= x0; \
    x0 += x1; x1 = __funnelshift_l(x1, x1, (b)); x1 ^= x0; \
    x0 += x1; x1 = __funnelshift_l(x1, x1, (c)); x1 ^= x0; \
    x0 += x1; x1 = __funnelshift_l(x1, x1, (d)); x1 ^= x0;
    R4(13,15,26,6)
    x0 += k1; x1 += k2 + 1u;
    R4(17,29,16,24)
    x0 += k2; x1 += k0 + 2u;
    R4(13,15,26,6)
    x0 += k0; x1 += k1 + 3u;
    R4(17,29,16,24)
    x0 += k1; x1 += k2 + 4u;
    R4(13,15,26,6)
    x0 += k2; x1 += k0 + 5u;
#undef R4
    return x0 ^ x1;
}

// host threefry block (for key derivation): returns both words
static void h_threefry(uint32_t k0, uint32_t k1, uint32_t x0, uint32_t x1,
                       uint32_t* o0, uint32_t* o1) {
    uint32_t k2 = k0 ^ k1 ^ 0x1BD11BDAu;
#define TFR(r) { x0 += x1; x1 = (x1 << (r)) | (x1 >> (32 - (r))); x1 ^= x0; }
    x0 += k0; x1 += k1;
    TFR(13) TFR(15) TFR(26) TFR(6)
    x0 += k1; x1 += k2 + 1u;
    TFR(17) TFR(29) TFR(16) TFR(24)
    x0 += k2; x1 += k0 + 2u;
    TFR(13) TFR(15) TFR(26) TFR(6)
    x0 += k0; x1 += k1 + 3u;
    TFR(17) TFR(29) TFR(16) TFR(24)
    x0 += k1; x1 += k2 + 4u;
    TFR(13) TFR(15) TFR(26) TFR(6)
    x0 += k2; x1 += k0 + 5u;
#undef TFR
    *o0 = x0; *o1 = x1;
}

// keep iff uniform < 0.9f  <=>  (bits>>9) < 7549747  (0.9f == 7549747 * 2^-23)
__device__ __forceinline__ float drop_apply(float v, uint32_t k0, uint32_t k1, uint32_t idx) {
    uint32_t bits = tf20_fold(k0, k1, idx);
    return ((bits >> 9) < 7549747u) ? v * (1.0f / 0.9f) : 0.0f;
}

// ---------------- CSR build ----------------
__global__ void k_zero_cnt(int n) {
    int i = blockIdx.x * blockDim.x + threadIdx.x;
    if (i < n) g_cnt[i] = 0;
}

__global__ void k_hist(const int* __restrict__ rows, int nnz) {
    int i = blockIdx.x * blockDim.x + threadIdx.x;
    if (i < nnz) atomicAdd(&g_cnt[rows[i]], 1);
}

__global__ void k_scan(int n) {
    __shared__ int sh[1024];
    int tid = threadIdx.x;
    int offset = 0;
    for (int base = 0; base < n; base += 1024) {
        int i = base + tid;
        int v = (i < n) ? g_cnt[i] : 0;
        sh[tid] = v;
        __syncthreads();
#pragma unroll
        for (int s = 1; s < 1024; s <<= 1) {
            int t = (tid >= s) ? sh[tid - s] : 0;
            __syncthreads();
            sh[tid] += t;
            __syncthreads();
        }
        int incl = sh[tid];
        int excl = incl - v;
        if (i < n) { g_rowptr[i] = offset + excl; g_rowfill[i] = offset + excl; }
        int total = sh[1023];
        __syncthreads();
        offset += total;
    }
    if (tid == 0) g_rowptr[n] = offset;
}

__global__ void k_scatter(const int* __restrict__ rows, const int* __restrict__ cols,
                          const float* __restrict__ vals, int nnz) {
    int i = blockIdx.x * blockDim.x + threadIdx.x;
    if (i < nnz) {
        int r = rows[i];
        int p = atomicAdd(&g_rowfill[r], 1);
        g_ccol[p] = cols[i];
        g_cval[p] = vals[i];
    }
}

// ---------------- gather x = embed[x_idx]; write out[:,0:256] and bufA ----------------
__global__ void k_gather(const int* __restrict__ idx, const float* __restrict__ emb,
                         float* __restrict__ out, int n) {
    int t = blockIdx.x * blockDim.x + threadIdx.x;
    int total = n * (HID / 4);
    if (t >= total) return;
    int row = t / (HID / 4);
    int c4  = (t % (HID / 4)) * 4;
    int src = __ldg(&idx[row]);
    float4 v = *(const float4*)(emb + (size_t)src * HID + c4);
    *(float4*)(g_bufA + (size_t)row * HID + c4) = v;
    *(float4*)(out + (size_t)row * OUTC + c4) = v;
}

// ---------------- fused spmm + residual + dropout ----------------
// outB[r,:] = dropout( sum_e val*x[col] + x[r,:] ),  mask idx = r*256 + c
__global__ void k_spmm_drop(const float* __restrict__ x, float* __restrict__ outB,
                            int n, uint32_t k0, uint32_t k1) {
    int row = (blockIdx.x * blockDim.x + threadIdx.x) >> 5;
    if (row >= n) return;
    int lane = threadIdx.x & 31;
    int s = g_rowptr[row], e = g_rowptr[row + 1];
    float4 acc0 = make_float4(0.f, 0.f, 0.f, 0.f);
    float4 acc1 = make_float4(0.f, 0.f, 0.f, 0.f);
    for (int p = s; p < e; ++p) {
        int   col = __ldg(&g_ccol[p]);
        float v   = __ldg(&g_cval[p]);
        const float4* xr = (const float4*)(x + (size_t)col * HID);
        float4 a = __ldg(&xr[lane]);
        float4 b = __ldg(&xr[32 + lane]);
        acc0.x += v * a.x; acc0.y += v * a.y; acc0.z += v * a.z; acc0.w += v * a.w;
        acc1.x += v * b.x; acc1.y += v * b.y; acc1.z += v * b.z; acc1.w += v * b.w;
    }
    const float4* hr = (const float4*)(x + (size_t)row * HID);
    float4 h0 = hr[lane], h1 = hr[32 + lane];
    acc0.x += h0.x; acc0.y += h0.y; acc0.z += h0.z; acc0.w += h0.w;
    acc1.x += h1.x; acc1.y += h1.y; acc1.z += h1.z; acc1.w += h1.w;

    uint32_t base = (uint32_t)row * 256u + (uint32_t)lane * 4u;
    acc0.x = drop_apply(acc0.x, k0, k1, base + 0u);
    acc0.y = drop_apply(acc0.y, k0, k1, base + 1u);
    acc0.z = drop_apply(acc0.z, k0, k1, base + 2u);
    acc0.w = drop_apply(acc0.w, k0, k1, base + 3u);
    acc1.x = drop_apply(acc1.x, k0, k1, base + 128u);
    acc1.y = drop_apply(acc1.y, k0, k1, base + 129u);
    acc1.z = drop_apply(acc1.z, k0, k1, base + 130u);
    acc1.w = drop_apply(acc1.w, k0, k1, base + 131u);

    float4* orow = (float4*)(outB + (size_t)row * HID);
    orow[lane] = acc0;
    orow[32 + lane] = acc1;
}

// ---------------- SGEMM: C = leaky(A @ W^T + b), A [NPAD,256], W [O,256] ----------------
#define BM 128
#define BN 128
#define BK 16

__global__ __launch_bounds__(256) void k_gemm(const float* __restrict__ A,
                                              const float* __restrict__ W,
                                              const float* __restrict__ bias,
                                              float* __restrict__ bufNext,
                                              float* __restrict__ outBase,
                                              int n) {
    __shared__ float As[BK][BM + 4];
    __shared__ float Bs[BK][BN + 4];
    int tid = threadIdx.x;
    int brow = blockIdx.x * BM;
    int bcol = blockIdx.y * BN;
    int tx = tid & 15, ty = tid >> 4;

    float acc[8][8];
#pragma unroll
    for (int i = 0; i < 8; ++i)
#pragma unroll
        for (int j = 0; j < 8; ++j) acc[i][j] = 0.f;

    int lr = tid >> 2;          // 0..63
    int lk = (tid & 3) * 4;     // 0,4,8,12
    const float* Aptr = A + (size_t)(brow + lr) * HID;
    const float* Wptr = W + (size_t)(bcol + lr) * HID;

    for (int k0 = 0; k0 < HID; k0 += BK) {
        float4 a0 = *(const float4*)(Aptr + k0 + lk);
        float4 a1 = *(const float4*)(Aptr + (size_t)64 * HID + k0 + lk);
        float4 b0 = *(const float4*)(Wptr + k0 + lk);
        float4 b1 = *(const float4*)(Wptr + (size_t)64 * HID + k0 + lk);
        __syncthreads();
        As[lk + 0][lr] = a0.x; As[lk + 1][lr] = a0.y; As[lk + 2][lr] = a0.z; As[lk + 3][lr] = a0.w;
        As[lk + 0][64 + lr] = a1.x; As[lk + 1][64 + lr] = a1.y; As[lk + 2][64 + lr] = a1.z; As[lk + 3][64 + lr] = a1.w;
        Bs[lk + 0][lr] = b0.x; Bs[lk + 1][lr] = b0.y; Bs[lk + 2][lr] = b0.z; Bs[lk + 3][lr] = b0.w;
        Bs[lk + 0][64 + lr] = b1.x; Bs[lk + 1][64 + lr] = b1.y; Bs[lk + 2][64 + lr] = b1.z; Bs[lk + 3][64 + lr] = b1.w;
        __syncthreads();
#pragma unroll
        for (int kk = 0; kk < BK; ++kk) {
            float ra[8], rb[8];
            *(float4*)(ra)     = *(const float4*)(&As[kk][ty * 8]);
            *(float4*)(ra + 4) = *(const float4*)(&As[kk][ty * 8 + 4]);
            *(float4*)(rb)     = *(const float4*)(&Bs[kk][tx * 8]);
            *(float4*)(rb + 4) = *(const float4*)(&Bs[kk][tx * 8 + 4]);
#pragma unroll
            for (int i = 0; i < 8; ++i)
#pragma unroll
                for (int j = 0; j < 8; ++j)
                    acc[i][j] += ra[i] * rb[j];
        }
    }

#pragma unroll
    for (int i = 0; i < 8; ++i) {
        int r = brow + ty * 8 + i;
#pragma unroll
        for (int j = 0; j < 8; ++j) {
            int c = bcol + tx * 8 + j;
            float v = acc[i][j] + __ldg(&bias[c]);
            v = (v >= 0.f) ? v : 0.2f * v;
            if (bufNext) bufNext[(size_t)r * HID + c] = v;
            if (r < n) outBase[(size_t)r * OUTC + c] = v;
        }
    }
}

// ---------------- launch ----------------
extern "C" void kernel_launch(void* const* d_in, const int* in_sizes, int n_in,
                              void* d_out, int out_size) {
    const int*   x_idx = (const int*)d_in[0];
    const float* emb   = (const float*)d_in[1];
    const int*   Grows = (const int*)d_in[2];
    const int*   Gcols = (const int*)d_in[3];
    const float* Gvals = (const float*)d_in[4];
    const float* W1 = (const float*)d_in[5];  const float* b1 = (const float*)d_in[6];
    const float* W2 = (const float*)d_in[7];  const float* b2 = (const float*)d_in[8];
    const float* W3 = (const float*)d_in[9];  const float* b3 = (const float*)d_in[10];
    float* out = (float*)d_out;

    int n   = in_sizes[0];
    int nnz = in_sizes[2];
    if (n > N_MAX) n = N_MAX;
    if (nnz > NNZ_MAX) nnz = NNZ_MAX;
    int npad = ((n + 127) / 128) * 128;

    // dropout keys: PARTITIONABLE (foldlike) split of key(42) into 3:
    // key_j = full threefry output pair for counts (hi=0, lo=j)
    uint32_t keys[3][2];
    for (int j = 0; j < 3; ++j)
        h_threefry(0u, 42u, 0u, (uint32_t)j, &keys[j][0], &keys[j][1]);

    float *bufA, *bufB;
    cudaGetSymbolAddress((void**)&bufA, g_bufA);
    cudaGetSymbolAddress((void**)&bufB, g_bufB);

    // CSR build
    k_zero_cnt<<<(n + 255) / 256, 256>>>(n);
    k_hist<<<(nnz + 255) / 256, 256>>>(Grows, nnz);
    k_scan<<<1, 1024>>>(n);
    k_scatter<<<(nnz + 255) / 256, 256>>>(Grows, Gcols, Gvals, nnz);

    // x = embed[x_idx] -> bufA and out[:,0:256]
    k_gather<<<(n * (HID / 4) + 255) / 256, 256>>>(x_idx, emb, out, n);

    int spmmBlocks = (n + 7) / 8;
    dim3 gemmGrid(npad / 128, 2);
    dim3 gemmGrid3(npad / 128, 1);

    // layer 1
    k_spmm_drop<<<spmmBlocks, 256>>>(bufA, bufB, n, keys[0][0], keys[0][1]);
    k_gemm<<<gemmGrid, 256>>>(bufB, W1, b1, bufA, out + 256, n);

    // layer 2
    k_spmm_drop<<<spmmBlocks, 256>>>(bufA, bufB, n, keys[1][0], keys[1][1]);
    k_gemm<<<gemmGrid, 256>>>(bufB, W2, b2, bufA, out + 512, n);

    // layer 3 (output dim 128)
    k_spmm_drop<<<spmmBlocks, 256>>>(bufA, bufB, n, keys[2][0], keys[2][1]);
    k_gemm<<<gemmGrid3, 256>>>(bufB, W3, b3, nullptr, out + 768, n);
}